// round 1
// baseline (speedup 1.0000x reference)
#include <cuda_runtime.h>
#include <cstdint>
#include <cstddef>

#define MAXN 100000
#define MAXE 800000
#define D128 128

// ---------------- scratch (no allocs allowed) ----------------
__device__ float d_bufA[(size_t)MAXN * D128];
__device__ float d_bufB[(size_t)MAXN * D128];
__device__ float d_aggrF[(size_t)MAXN * D128];
__device__ float d_aggrV[(size_t)MAXN * D128];
__device__ float d_Vc[(size_t)MAXN * D128];
__device__ float d_Fc[(size_t)MAXN * D128];
__device__ float d_gatt[64 * D128];
__device__ float d_gate[MAXN];
__device__ float d_ebuf[MAXN];
__device__ int   d_offF[MAXN + 1];
__device__ int   d_offV[MAXN + 1];
__device__ int   d_curF[MAXN];
__device__ int   d_curV[MAXN];
__device__ int   d_adjF[MAXE];
__device__ int   d_adjV[MAXE];
__device__ int   d_bnd[65 + 4];

// ---------------- f32x2 packed helpers ----------------
__device__ __forceinline__ unsigned long long pk2(float x) {
    unsigned int u = __float_as_uint(x);
    unsigned long long r;
    asm("mov.b64 %0, {%1, %1};" : "=l"(r) : "r"(u));
    return r;
}
__device__ __forceinline__ void ffma2(unsigned long long &d, unsigned long long a, unsigned long long b) {
    asm("fma.rn.f32x2 %0, %1, %2, %0;" : "+l"(d) : "l"(a), "l"(b));
}
__device__ __forceinline__ float2 upk2(unsigned long long v) {
    unsigned int lo, hi;
    asm("mov.b64 {%0, %1}, %2;" : "=r"(lo), "=r"(hi) : "l"(v));
    return make_float2(__uint_as_float(lo), __uint_as_float(hi));
}

// ---------------- SGEMM: Out[M,128] = op( A[M,128]@W(0:128) (+ B[M,128]@W(128:256)) + bias ) ----------------
// flags bit0: relu ; Res != null -> Out = Res + result (residual added AFTER relu)
__global__ void __launch_bounds__(256, 2) gemm_kernel(
    const float* __restrict__ A, const float* __restrict__ B,
    const float* __restrict__ W, const float* __restrict__ bias,
    const float* __restrict__ Res, float* __restrict__ Out,
    int M, int flags)
{
    const int K = (B != nullptr) ? 256 : 128;
    __shared__ __align__(16) float As[32][132];  // transposed A tile [k][row]
    __shared__ __align__(16) float Ws[32][128];  // [k][col]

    const int tid = threadIdx.x;
    const int tx = tid & 15;   // col group (8 cols each)
    const int ty = tid >> 4;   // row group (8 rows each)
    const int rowBase = blockIdx.x * 128;

    unsigned long long acc[8][4];
#pragma unroll
    for (int i = 0; i < 8; i++)
#pragma unroll
        for (int j = 0; j < 4; j++) acc[i][j] = 0ull;

    for (int k0 = 0; k0 < K; k0 += 32) {
        const float* Asrc = (k0 < 128) ? A : B;
        const int kb = (k0 < 128) ? k0 : (k0 - 128);
        // load A tile: 128 rows x 32 cols, transposed into As
#pragma unroll
        for (int h = 0; h < 4; h++) {
            int idx = tid + h * 256;          // float4 index, 1024 total
            int r = idx >> 3;                 // 0..127
            int c = (idx & 7) << 2;           // 0..28
            int grow = rowBase + r;
            float4 v = make_float4(0.f, 0.f, 0.f, 0.f);
            if (grow < M) v = *reinterpret_cast<const float4*>(Asrc + (size_t)grow * 128 + kb + c);
            As[c + 0][r] = v.x; As[c + 1][r] = v.y; As[c + 2][r] = v.z; As[c + 3][r] = v.w;
        }
        // load W tile: 32 x 128
#pragma unroll
        for (int h = 0; h < 4; h++) {
            int idx = tid + h * 256;
            int r = idx >> 5;                 // 0..31
            int c = (idx & 31) << 2;          // 0..124
            *reinterpret_cast<float4*>(&Ws[r][c]) =
                *reinterpret_cast<const float4*>(W + (size_t)(k0 + r) * 128 + c);
        }
        __syncthreads();
#pragma unroll
        for (int kk = 0; kk < 32; kk++) {
            float4 a0 = *reinterpret_cast<const float4*>(&As[kk][ty * 8]);
            float4 a1 = *reinterpret_cast<const float4*>(&As[kk][ty * 8 + 4]);
            ulonglong2 w0 = *reinterpret_cast<const ulonglong2*>(&Ws[kk][tx * 8]);
            ulonglong2 w1 = *reinterpret_cast<const ulonglong2*>(&Ws[kk][tx * 8 + 4]);
            unsigned long long ap[8];
            ap[0] = pk2(a0.x); ap[1] = pk2(a0.y); ap[2] = pk2(a0.z); ap[3] = pk2(a0.w);
            ap[4] = pk2(a1.x); ap[5] = pk2(a1.y); ap[6] = pk2(a1.z); ap[7] = pk2(a1.w);
            unsigned long long wp[4] = { w0.x, w0.y, w1.x, w1.y };
#pragma unroll
            for (int i = 0; i < 8; i++)
#pragma unroll
                for (int j = 0; j < 4; j++)
                    ffma2(acc[i][j], ap[i], wp[j]);
        }
        __syncthreads();
    }

    const bool relu = (flags & 1);
    const int col = tx * 8;
#pragma unroll
    for (int i = 0; i < 8; i++) {
        int grow = rowBase + ty * 8 + i;
        if (grow < M) {
            float o[8];
#pragma unroll
            for (int j = 0; j < 4; j++) {
                float2 f = upk2(acc[i][j]);
                o[2 * j] = f.x; o[2 * j + 1] = f.y;
            }
            if (bias) {
#pragma unroll
                for (int j = 0; j < 8; j++) o[j] += bias[col + j];
            }
            if (relu) {
#pragma unroll
                for (int j = 0; j < 8; j++) o[j] = fmaxf(o[j], 0.f);
            }
            if (Res) {
#pragma unroll
                for (int j = 0; j < 8; j++) o[j] += Res[(size_t)grow * 128 + col + j];
            }
            *reinterpret_cast<float4*>(Out + (size_t)grow * 128 + col) = make_float4(o[0], o[1], o[2], o[3]);
            *reinterpret_cast<float4*>(Out + (size_t)grow * 128 + col + 4) = make_float4(o[4], o[5], o[6], o[7]);
        }
    }
}

// ---------------- CSR build ----------------
__global__ void hist_kernel(const int* __restrict__ src, const int* __restrict__ dst, int E,
                            int* __restrict__ degV, int* __restrict__ degF)
{
    int e = blockIdx.x * blockDim.x + threadIdx.x;
    if (e < E) {
        atomicAdd(&degV[src[e]], 1);
        atomicAdd(&degF[dst[e]], 1);
    }
}

__device__ void scan_excl_dev(int* deg, int* offs, int N)
{
    __shared__ int warpsum[32];
    __shared__ int carry;
    const int t = threadIdx.x, lane = t & 31, wid = t >> 5;
    const int nwarp = blockDim.x >> 5;
    if (t == 0) carry = 0;
    __syncthreads();
    for (int base = 0; base < N; base += blockDim.x) {
        int i = base + t;
        int v = (i < N) ? deg[i] : 0;
        int x = v;
#pragma unroll
        for (int d = 1; d < 32; d <<= 1) { int y = __shfl_up_sync(~0u, x, d); if (lane >= d) x += y; }
        if (lane == 31) warpsum[wid] = x;
        __syncthreads();
        if (wid == 0) {
            int w = (lane < nwarp) ? warpsum[lane] : 0;
#pragma unroll
            for (int d = 1; d < 32; d <<= 1) { int y = __shfl_up_sync(~0u, w, d); if (lane >= d) w += y; }
            warpsum[lane] = w;
        }
        __syncthreads();
        int incl = x + (wid > 0 ? warpsum[wid - 1] : 0);
        int excl = carry + incl - v;
        if (i < N) { offs[i] = excl; deg[i] = excl; }  // deg doubles as scatter cursor
        int total = warpsum[nwarp - 1];
        __syncthreads();
        if (t == 0) carry += total;
        __syncthreads();
    }
    if (t == 0) offs[N] = carry;
}

__global__ void scan2_kernel(int* degF, int* offF, int NF, int* degV, int* offV, int NV)
{
    if (blockIdx.x == 0) scan_excl_dev(degF, offF, NF);
    else                 scan_excl_dev(degV, offV, NV);
}

__global__ void scatter_kernel(const int* __restrict__ src, const int* __restrict__ dst, int E,
                               int* __restrict__ curV, int* __restrict__ curF,
                               int* __restrict__ adjV, int* __restrict__ adjF)
{
    int e = blockIdx.x * blockDim.x + threadIdx.x;
    if (e < E) {
        int s = src[e], d = dst[e];
        adjF[atomicAdd(&curF[d], 1)] = s;   // factor side stores variable partner
        adjV[atomicAdd(&curV[s], 1)] = d;   // variable side stores factor partner
    }
}

// ---------------- CSR gather-reduce: out[n] = sum_e relu(Pself[n] + Pother[adj[e]] + bias) ----------------
__global__ void csr_reduce_kernel(const int* __restrict__ offs, const int* __restrict__ adj,
                                  const float* __restrict__ Pself, const float* __restrict__ Pother,
                                  const float* __restrict__ bias, float* __restrict__ out, int N)
{
    int w = (blockIdx.x * blockDim.x + threadIdx.x) >> 5;
    int lane = threadIdx.x & 31;
    if (w >= N) return;
    const int c = lane * 4;
    float4 s = *reinterpret_cast<const float4*>(Pself + (size_t)w * 128 + c);
    float4 b = *reinterpret_cast<const float4*>(bias + c);
    s.x += b.x; s.y += b.y; s.z += b.z; s.w += b.w;
    float4 acc = make_float4(0.f, 0.f, 0.f, 0.f);
    int e = offs[w], e1 = offs[w + 1];
    for (; e + 1 < e1; e += 2) {
        int n0 = __ldg(adj + e);
        int n1 = __ldg(adj + e + 1);
        float4 o0 = *reinterpret_cast<const float4*>(Pother + (size_t)n0 * 128 + c);
        float4 o1 = *reinterpret_cast<const float4*>(Pother + (size_t)n1 * 128 + c);
        acc.x += fmaxf(s.x + o0.x, 0.f) + fmaxf(s.x + o1.x, 0.f);
        acc.y += fmaxf(s.y + o0.y, 0.f) + fmaxf(s.y + o1.y, 0.f);
        acc.z += fmaxf(s.z + o0.z, 0.f) + fmaxf(s.z + o1.z, 0.f);
        acc.w += fmaxf(s.w + o0.w, 0.f) + fmaxf(s.w + o1.w, 0.f);
    }
    if (e < e1) {
        int n0 = __ldg(adj + e);
        float4 o0 = *reinterpret_cast<const float4*>(Pother + (size_t)n0 * 128 + c);
        acc.x += fmaxf(s.x + o0.x, 0.f);
        acc.y += fmaxf(s.y + o0.y, 0.f);
        acc.z += fmaxf(s.z + o0.z, 0.f);
        acc.w += fmaxf(s.w + o0.w, 0.f);
    }
    *reinterpret_cast<float4*>(out + (size_t)w * 128 + c) = acc;
}

// ---------------- global node ----------------
__global__ void gate_kernel(const float* __restrict__ F, const float* __restrict__ Wg,
                            const float* __restrict__ bg, float* __restrict__ gate, int N)
{
    int w = (blockIdx.x * blockDim.x + threadIdx.x) >> 5;
    int lane = threadIdx.x & 31;
    if (w >= N) return;
    float4 f = *reinterpret_cast<const float4*>(F + (size_t)w * 128 + lane * 4);
    float4 g = *reinterpret_cast<const float4*>(Wg + lane * 4);
    float p = f.x * g.x + f.y * g.y + f.z * g.z + f.w * g.w;
#pragma unroll
    for (int d = 16; d; d >>= 1) p += __shfl_down_sync(~0u, p, d);
    if (lane == 0) gate[w] = p + bg[0];
}

__global__ void bounds_kernel(const int* __restrict__ batch, int NF, int G, int* __restrict__ bnd)
{
    int g = threadIdx.x;
    if (g > G) return;
    int lo = 0, hi = NF;
    while (lo < hi) { int mid = (lo + hi) >> 1; if (batch[mid] < g) lo = mid + 1; else hi = mid; }
    bnd[g] = lo;
}

__global__ void group_kernel(const float* __restrict__ gate, const int* __restrict__ bnd,
                             const float* __restrict__ T, float* __restrict__ ebuf,
                             float* __restrict__ gatt)
{
    __shared__ float red[256];
    __shared__ float s_mx, s_den;
    const int g = blockIdx.x;
    const int s = bnd[g], e = bnd[g + 1];
    const int t = threadIdx.x;
    float mx = -1e30f;
    for (int i = s + t; i < e; i += 256) mx = fmaxf(mx, gate[i]);
    red[t] = mx; __syncthreads();
    for (int o = 128; o; o >>= 1) { if (t < o) red[t] = fmaxf(red[t], red[t + o]); __syncthreads(); }
    if (t == 0) s_mx = red[0];
    __syncthreads();
    float den = 0.f;
    for (int i = s + t; i < e; i += 256) { float ex = __expf(gate[i] - s_mx); ebuf[i] = ex; den += ex; }
    red[t] = den; __syncthreads();
    for (int o = 128; o; o >>= 1) { if (t < o) red[t] += red[t + o]; __syncthreads(); }
    if (t == 0) s_den = red[0];
    __syncthreads();
    if (t < 128) {
        float acc = 0.f;
        for (int i = s; i < e; i++) acc += ebuf[i] * T[(size_t)i * 128 + t];
        gatt[g * 128 + t] = (e > s) ? (acc / s_den) : 0.f;
    }
}

// ---------------- launch ----------------
extern "C" void kernel_launch(void* const* d_in, const int* in_sizes, int n_in,
                              void* d_out, int out_size)
{
    const float* V_in  = (const float*)d_in[0];
    const float* F_in  = (const float*)d_in[1];
    const int*   eidx  = (const int*)d_in[2];
    // d_in[3] edge_attr: unused by the reference math
    const int*   batch = (const int*)d_in[4];
    const float* Wm_vf = (const float*)d_in[5];
    const float* bm_vf = (const float*)d_in[6];
    const float* Wc_vf = (const float*)d_in[7];
    const float* bc_vf = (const float*)d_in[8];
    const float* Wm_fv = (const float*)d_in[9];
    const float* bm_fv = (const float*)d_in[10];
    const float* Wc_fv = (const float*)d_in[11];
    const float* bc_fv = (const float*)d_in[12];
    const float* Wg    = (const float*)d_in[13];
    const float* bg    = (const float*)d_in[14];
    const float* Wt    = (const float*)d_in[15];
    const float* bt    = (const float*)d_in[16];
    const float* Wl    = (const float*)d_in[17];
    const float* bl    = (const float*)d_in[18];

    const int NV = in_sizes[0] / D128;
    const int NF = in_sizes[1] / D128;
    const int E  = in_sizes[2] / 2;
    const int G  = out_size / D128 - NV - NF;
    const int* src  = eidx;
    const int* dstf = eidx + E;

    float *bufA, *bufB, *aggrF, *aggrV, *Vc, *Fc, *gatt, *gateArr, *ebuf;
    int *offF, *offV, *curF, *curV, *adjF, *adjV, *bnd;
    cudaGetSymbolAddress((void**)&bufA,  d_bufA);
    cudaGetSymbolAddress((void**)&bufB,  d_bufB);
    cudaGetSymbolAddress((void**)&aggrF, d_aggrF);
    cudaGetSymbolAddress((void**)&aggrV, d_aggrV);
    cudaGetSymbolAddress((void**)&Vc,    d_Vc);
    cudaGetSymbolAddress((void**)&Fc,    d_Fc);
    cudaGetSymbolAddress((void**)&gatt,  d_gatt);
    cudaGetSymbolAddress((void**)&gateArr, d_gate);
    cudaGetSymbolAddress((void**)&ebuf,  d_ebuf);
    cudaGetSymbolAddress((void**)&offF,  d_offF);
    cudaGetSymbolAddress((void**)&offV,  d_offV);
    cudaGetSymbolAddress((void**)&curF,  d_curF);
    cudaGetSymbolAddress((void**)&curV,  d_curV);
    cudaGetSymbolAddress((void**)&adjF,  d_adjF);
    cudaGetSymbolAddress((void**)&adjV,  d_adjV);
    cudaGetSymbolAddress((void**)&bnd,   d_bnd);

    // ---- CSR build (both directions) ----
    cudaMemsetAsync(curF, 0, (size_t)NF * sizeof(int));
    cudaMemsetAsync(curV, 0, (size_t)NV * sizeof(int));
    hist_kernel<<<(E + 255) / 256, 256>>>(src, dstf, E, curV, curF);
    scan2_kernel<<<2, 1024>>>(curF, offF, NF, curV, offV, NV);
    scatter_kernel<<<(E + 255) / 256, 256>>>(src, dstf, E, curV, curF, adjV, adjF);

    const int gF = (NF + 127) / 128;
    const int gV = (NV + 127) / 128;

    float* outV_final = (float*)d_out;
    float* outF_final = (float*)d_out + (size_t)NV * D128;
    float* g_out      = (float*)d_out + (size_t)(NV + NF) * D128;

    const float* Vp = V_in;
    const float* Fp = F_in;

    for (int l = 0; l < 2; l++) {
        const float* WmVF = Wm_vf + (size_t)l * 256 * 128;
        const float* WmFV = Wm_fv + (size_t)l * 256 * 128;
        const float* WcVF = Wc_vf + (size_t)l * 256 * 128;
        const float* WcFV = Wc_fv + (size_t)l * 256 * 128;

        // var->factor messages: Pf = F@Wm_vf_top, Pv = V@Wm_vf_bot
        gemm_kernel<<<gF, 256>>>(Fp, nullptr, WmVF,            nullptr, nullptr, bufA, NF, 0);
        gemm_kernel<<<gV, 256>>>(Vp, nullptr, WmVF + 128 * 128, nullptr, nullptr, bufB, NV, 0);
        csr_reduce_kernel<<<(NF + 7) / 8, 256>>>(offF, adjF, bufA, bufB, bm_vf + l * 128, aggrF, NF);

        // factor->var messages (uses OLD factors): Qv = V@Wm_fv_top, Qf = F@Wm_fv_bot
        gemm_kernel<<<gV, 256>>>(Vp, nullptr, WmFV,            nullptr, nullptr, bufA, NV, 0);
        gemm_kernel<<<gF, 256>>>(Fp, nullptr, WmFV + 128 * 128, nullptr, nullptr, bufB, NF, 0);
        csr_reduce_kernel<<<(NV + 7) / 8, 256>>>(offV, adjV, bufA, bufB, bm_fv + l * 128, aggrV, NV);

        float* oF = (l == 1) ? outF_final : Fc;
        float* oV = (l == 1) ? outV_final : Vc;
        // newF = relu(F@Wc_top + aggrF@Wc_bot + bc)
        gemm_kernel<<<gF, 256>>>(Fp, aggrF, WcVF, bc_vf + l * 128, nullptr, oF, NF, 1);
        // newV = V + relu(V@Wc_top + aggrV@Wc_bot + bc)
        gemm_kernel<<<gV, 256>>>(Vp, aggrV, WcFV, bc_fv + l * 128, Vp, oV, NV, 1);
        Fp = oF; Vp = oV;
    }

    // ---- global node: attentional aggregation over factors ----
    gate_kernel<<<(NF + 7) / 8, 256>>>(Fp, Wg, bg, gateArr, NF);
    gemm_kernel<<<gF, 256>>>(Fp, nullptr, Wt, bt, nullptr, bufA, NF, 0);     // T = F@Wt + bt
    bounds_kernel<<<1, 128>>>(batch, NF, G, bnd);
    group_kernel<<<G, 256>>>(gateArr, bnd, bufA, ebuf, gatt);
    // g = relu(g_att @ Wl_top + bl)   (g_prev = 0)
    gemm_kernel<<<1, 256>>>(gatt, nullptr, Wl, bl, nullptr, g_out, G, 1);
}

// round 3
// speedup vs baseline: 1.5313x; 1.5313x over previous
#include <cuda_runtime.h>
#include <cstdint>
#include <cstddef>

#define MAXN 100000
#define MAXE 800000
#define D128 128

// ---------------- scratch (no allocs allowed) ----------------
__device__ float d_bufA[(size_t)MAXN * D128];   // Pf / T
__device__ float d_bufB[(size_t)MAXN * D128];   // Pv
__device__ float d_bufC[(size_t)MAXN * D128];   // Qf
__device__ float d_bufD[(size_t)MAXN * D128];   // Qv
__device__ float d_aggrF[(size_t)MAXN * D128];
__device__ float d_aggrV[(size_t)MAXN * D128];
__device__ float d_Vc[(size_t)MAXN * D128];
__device__ float d_Fc[(size_t)MAXN * D128];
__device__ float d_WT[294912];                  // pre-transposed weights
__device__ float d_gatt[64 * D128];
__device__ float d_gate[MAXN];
__device__ float d_ebuf[MAXN];
__device__ int   d_offF[MAXN + 1];
__device__ int   d_offV[MAXN + 1];
__device__ int   d_curF[MAXN];
__device__ int   d_curV[MAXN];
__device__ int   d_adjF[MAXE];
__device__ int   d_adjV[MAXE];
__device__ int   d_bnd[65 + 4];

// ---------------- PTX helpers ----------------
__device__ __forceinline__ uint32_t smem_u32(const void* p) {
    uint32_t a;
    asm("{ .reg .u64 t; cvta.to.shared.u64 t, %1; cvt.u32.u64 %0, t; }" : "=r"(a) : "l"(p));
    return a;
}
__device__ __forceinline__ uint32_t f2tf(float x) {
    uint32_t r;
    asm("cvt.rn.tf32.f32 %0, %1;" : "=r"(r) : "f"(x));
    return r;
}
__device__ __forceinline__ void ldsm_x4(uint32_t& r0, uint32_t& r1, uint32_t& r2, uint32_t& r3, uint32_t addr) {
    asm volatile("ldmatrix.sync.aligned.m8n8.x4.shared.b16 {%0,%1,%2,%3}, [%4];"
                 : "=r"(r0), "=r"(r1), "=r"(r2), "=r"(r3) : "r"(addr));
}
__device__ __forceinline__ void mma_tf32(float* c, const uint32_t* a, uint32_t b0, uint32_t b1) {
    asm volatile(
        "mma.sync.aligned.m16n8k8.row.col.f32.tf32.tf32.f32 "
        "{%0,%1,%2,%3}, {%4,%5,%6,%7}, {%8,%9}, {%0,%1,%2,%3};"
        : "+f"(c[0]), "+f"(c[1]), "+f"(c[2]), "+f"(c[3])
        : "r"(a[0]), "r"(a[1]), "r"(a[2]), "r"(a[3]), "r"(b0), "r"(b1));
}

// ---------------- tf32 mma.sync GEMM ----------------
// Out[M,N] = op( A[M,K] @ WT^T + bias ); WT is [N,K] row-major (pre-transposed).
// K in {128,256}: k-chunks 0-3 read A0[M,128], 4-7 read A1[M,128].
// N = gridDim.y*128: blockIdx.y==0 writes Out0, ==1 writes Out1 (each [M,128]).
// relu applied before Res; Res added after relu (residual connection).
// Block: 512 threads = 16 warps (8M x 2N); block tile 128x128x32; warp tile 16x64.
#define SM_PITCH 36
#define STAGE_F (2 * 128 * SM_PITCH)   // floats per stage (A + B)
__global__ void __launch_bounds__(512, 1) gemm_mma(
    const float* __restrict__ A0, const float* __restrict__ A1,
    const float* __restrict__ WT,
    const float* __restrict__ bias, const float* __restrict__ Res,
    float* __restrict__ Out0, float* __restrict__ Out1,
    int M, int K, int relu)
{
    extern __shared__ __align__(16) float sm[];
    const int tid  = threadIdx.x;
    const int lane = tid & 31;
    const int warp = tid >> 5;
    const int wm = warp & 7;          // 0..7  (M direction, 16 rows each)
    const int wn = warp >> 3;         // 0..1  (N direction, 64 cols each)
    const int rowBase = blockIdx.x * 128;
    const int nblk = blockIdx.y;
    const float* WTb = WT + (size_t)nblk * 128 * K;
    float* Out = (nblk == 0) ? Out0 : Out1;

    // per-thread global load coords (2 x float4 each for A and B per k-chunk)
    const int gr = tid >> 3;              // 0..63 (+64 for h=1)
    const int gc = (tid & 7) << 2;        // 0,4,...,28

    // ldmatrix source offsets (in floats, within a stage)
    const int arow = wm * 16 + (lane & 15);
    const int acol = (lane >> 4) << 2;
    const int aoff = arow * SM_PITCH + acol;
    const int bq = lane >> 3;
    const int brow0 = wn * 64 + ((bq & 2) << 2) + (lane & 7);  // + p*16 later
    const int bcol = (bq & 1) << 2;
    const int boff = brow0 * SM_PITCH + bcol;

    float acc[8][4];
#pragma unroll
    for (int nt = 0; nt < 8; nt++)
#pragma unroll
        for (int j = 0; j < 4; j++) acc[nt][j] = 0.f;

    const int nch = K >> 5;
    uint4 ra[2], rb[2];

    // --- ldg chunk 0 ---
    {
        const float* Asrc = A0;
#pragma unroll
        for (int h = 0; h < 2; h++) {
            int r = gr + h * 64;
            int grow = rowBase + r;
            float4 v = make_float4(0.f, 0.f, 0.f, 0.f);
            if (grow < M) v = *reinterpret_cast<const float4*>(Asrc + (size_t)grow * 128 + gc);
            ra[h] = make_uint4(f2tf(v.x), f2tf(v.y), f2tf(v.z), f2tf(v.w));
            float4 w = *reinterpret_cast<const float4*>(WTb + (size_t)r * K + gc);
            rb[h] = make_uint4(f2tf(w.x), f2tf(w.y), f2tf(w.z), f2tf(w.w));
        }
    }

    const uint32_t smbase = smem_u32(sm);
    for (int ck = 0; ck < nch; ck++) {
        const int s = ck & 1;
        float* stA = sm + s * STAGE_F;
        float* stB = stA + 128 * SM_PITCH;
        // store staged regs
#pragma unroll
        for (int h = 0; h < 2; h++) {
            int r = gr + h * 64;
            *reinterpret_cast<uint4*>(stA + r * SM_PITCH + gc) = ra[h];
            *reinterpret_cast<uint4*>(stB + r * SM_PITCH + gc) = rb[h];
        }
        __syncthreads();
        // prefetch next chunk
        if (ck + 1 < nch) {
            int kg = (ck + 1) * 32;
            const float* Asrc = A0;
            if (kg >= 128) { Asrc = A1; kg -= 128; }
#pragma unroll
            for (int h = 0; h < 2; h++) {
                int r = gr + h * 64;
                int grow = rowBase + r;
                float4 v = make_float4(0.f, 0.f, 0.f, 0.f);
                if (grow < M) v = *reinterpret_cast<const float4*>(Asrc + (size_t)grow * 128 + kg + gc);
                ra[h] = make_uint4(f2tf(v.x), f2tf(v.y), f2tf(v.z), f2tf(v.w));
                float4 w = *reinterpret_cast<const float4*>(WTb + (size_t)r * K + (ck + 1) * 32 + gc);
                rb[h] = make_uint4(f2tf(w.x), f2tf(w.y), f2tf(w.z), f2tf(w.w));
            }
        }
        // compute on stage s
        const uint32_t smA = smbase + (s * STAGE_F) * 4;
        const uint32_t smB = smA + 128 * SM_PITCH * 4;
#pragma unroll
        for (int kk = 0; kk < 4; kk++) {
            uint32_t a[4];
            ldsm_x4(a[0], a[1], a[2], a[3], smA + (aoff + kk * 8) * 4);
            uint32_t b0[8], b1[8];
#pragma unroll
            for (int p = 0; p < 4; p++) {
                ldsm_x4(b0[2 * p], b1[2 * p], b0[2 * p + 1], b1[2 * p + 1],
                        smB + (boff + p * 16 * SM_PITCH + kk * 8) * 4);
            }
#pragma unroll
            for (int nt = 0; nt < 8; nt++)
                mma_tf32(acc[nt], a, b0[nt], b1[nt]);
        }
        __syncthreads();
    }

    // epilogue
    const int r0 = rowBase + wm * 16 + (lane >> 2);
    const int col2 = (lane & 3) * 2;
#pragma unroll
    for (int nt = 0; nt < 8; nt++) {
        int col = wn * 64 + nt * 8 + col2;
        float v0 = acc[nt][0], v1 = acc[nt][1], v2 = acc[nt][2], v3 = acc[nt][3];
        if (bias) {
            float b0 = bias[col], b1 = bias[col + 1];
            v0 += b0; v1 += b1; v2 += b0; v3 += b1;
        }
        if (relu) {
            v0 = fmaxf(v0, 0.f); v1 = fmaxf(v1, 0.f);
            v2 = fmaxf(v2, 0.f); v3 = fmaxf(v3, 0.f);
        }
        if (r0 < M) {
            if (Res) {
                float2 rr = *reinterpret_cast<const float2*>(Res + (size_t)r0 * 128 + col);
                v0 += rr.x; v1 += rr.y;
            }
            *reinterpret_cast<float2*>(Out + (size_t)r0 * 128 + col) = make_float2(v0, v1);
        }
        if (r0 + 8 < M) {
            if (Res) {
                float2 rr = *reinterpret_cast<const float2*>(Res + (size_t)(r0 + 8) * 128 + col);
                v2 += rr.x; v3 += rr.y;
            }
            *reinterpret_cast<float2*>(Out + (size_t)(r0 + 8) * 128 + col) = make_float2(v2, v3);
        }
    }
}

// ---------------- weight transpose: dst[n*K + k] = src[k*128 + n] ----------------
__global__ void transpose_kernel(const float* __restrict__ src, float* __restrict__ dst, int K)
{
    __shared__ float t[32][33];
    int kb = blockIdx.x * 32, nb = blockIdx.y * 32;
    int x = threadIdx.x, y = threadIdx.y;
    for (int yy = y; yy < 32; yy += 8) t[yy][x] = src[(size_t)(kb + yy) * 128 + nb + x];
    __syncthreads();
    for (int yy = y; yy < 32; yy += 8) dst[(size_t)(nb + yy) * K + kb + x] = t[x][yy];
}

// ---------------- CSR build ----------------
__global__ void hist_kernel(const int* __restrict__ src, const int* __restrict__ dst, int E,
                            int* __restrict__ degV, int* __restrict__ degF)
{
    int e = blockIdx.x * blockDim.x + threadIdx.x;
    if (e < E) {
        atomicAdd(&degV[src[e]], 1);
        atomicAdd(&degF[dst[e]], 1);
    }
}

__device__ void scan_excl_dev(int* deg, int* offs, int N)
{
    __shared__ int warpsum[32];
    __shared__ int carry;
    const int t = threadIdx.x, lane = t & 31, wid = t >> 5;
    const int nwarp = blockDim.x >> 5;
    if (t == 0) carry = 0;
    __syncthreads();
    for (int base = 0; base < N; base += blockDim.x) {
        int i = base + t;
        int v = (i < N) ? deg[i] : 0;
        int x = v;
#pragma unroll
        for (int d = 1; d < 32; d <<= 1) { int y = __shfl_up_sync(~0u, x, d); if (lane >= d) x += y; }
        if (lane == 31) warpsum[wid] = x;
        __syncthreads();
        if (wid == 0) {
            int w = (lane < nwarp) ? warpsum[lane] : 0;
#pragma unroll
            for (int d = 1; d < 32; d <<= 1) { int y = __shfl_up_sync(~0u, w, d); if (lane >= d) w += y; }
            warpsum[lane] = w;
        }
        __syncthreads();
        int incl = x + (wid > 0 ? warpsum[wid - 1] : 0);
        int excl = carry + incl - v;
        if (i < N) { offs[i] = excl; deg[i] = excl; }
        int total = warpsum[nwarp - 1];
        __syncthreads();
        if (t == 0) carry += total;
        __syncthreads();
    }
    if (t == 0) offs[N] = carry;
}

__global__ void scan2_kernel(int* degF, int* offF, int NF, int* degV, int* offV, int NV)
{
    if (blockIdx.x == 0) scan_excl_dev(degF, offF, NF);
    else                 scan_excl_dev(degV, offV, NV);
}

__global__ void scatter_kernel(const int* __restrict__ src, const int* __restrict__ dst, int E,
                               int* __restrict__ curV, int* __restrict__ curF,
                               int* __restrict__ adjV, int* __restrict__ adjF)
{
    int e = blockIdx.x * blockDim.x + threadIdx.x;
    if (e < E) {
        int s = src[e], d = dst[e];
        adjF[atomicAdd(&curF[d], 1)] = s;
        adjV[atomicAdd(&curV[s], 1)] = d;
    }
}

// ---------------- CSR gather-reduce ----------------
__global__ void csr_reduce_kernel(const int* __restrict__ offs, const int* __restrict__ adj,
                                  const float* __restrict__ Pself, const float* __restrict__ Pother,
                                  const float* __restrict__ bias, float* __restrict__ out, int N)
{
    int w = (blockIdx.x * blockDim.x + threadIdx.x) >> 5;
    int lane = threadIdx.x & 31;
    if (w >= N) return;
    const int c = lane * 4;
    float4 s = *reinterpret_cast<const float4*>(Pself + (size_t)w * 128 + c);
    float4 b = *reinterpret_cast<const float4*>(bias + c);
    s.x += b.x; s.y += b.y; s.z += b.z; s.w += b.w;
    float4 acc = make_float4(0.f, 0.f, 0.f, 0.f);
    int e = offs[w], e1 = offs[w + 1];
    for (; e + 1 < e1; e += 2) {
        int n0 = __ldg(adj + e);
        int n1 = __ldg(adj + e + 1);
        float4 o0 = *reinterpret_cast<const float4*>(Pother + (size_t)n0 * 128 + c);
        float4 o1 = *reinterpret_cast<const float4*>(Pother + (size_t)n1 * 128 + c);
        acc.x += fmaxf(s.x + o0.x, 0.f) + fmaxf(s.x + o1.x, 0.f);
        acc.y += fmaxf(s.y + o0.y, 0.f) + fmaxf(s.y + o1.y, 0.f);
        acc.z += fmaxf(s.z + o0.z, 0.f) + fmaxf(s.z + o1.z, 0.f);
        acc.w += fmaxf(s.w + o0.w, 0.f) + fmaxf(s.w + o1.w, 0.f);
    }
    if (e < e1) {
        int n0 = __ldg(adj + e);
        float4 o0 = *reinterpret_cast<const float4*>(Pother + (size_t)n0 * 128 + c);
        acc.x += fmaxf(s.x + o0.x, 0.f);
        acc.y += fmaxf(s.y + o0.y, 0.f);
        acc.z += fmaxf(s.z + o0.z, 0.f);
        acc.w += fmaxf(s.w + o0.w, 0.f);
    }
    *reinterpret_cast<float4*>(out + (size_t)w * 128 + c) = acc;
}

// ---------------- global node ----------------
__global__ void gate_kernel(const float* __restrict__ F, const float* __restrict__ Wg,
                            const float* __restrict__ bg, float* __restrict__ gate, int N)
{
    int w = (blockIdx.x * blockDim.x + threadIdx.x) >> 5;
    int lane = threadIdx.x & 31;
    if (w >= N) return;
    float4 f = *reinterpret_cast<const float4*>(F + (size_t)w * 128 + lane * 4);
    float4 g = *reinterpret_cast<const float4*>(Wg + lane * 4);
    float p = f.x * g.x + f.y * g.y + f.z * g.z + f.w * g.w;
#pragma unroll
    for (int d = 16; d; d >>= 1) p += __shfl_down_sync(~0u, p, d);
    if (lane == 0) gate[w] = p + bg[0];
}

__global__ void bounds_kernel(const int* __restrict__ batch, int NF, int G, int* __restrict__ bnd)
{
    int g = threadIdx.x;
    if (g > G) return;
    int lo = 0, hi = NF;
    while (lo < hi) { int mid = (lo + hi) >> 1; if (batch[mid] < g) lo = mid + 1; else hi = mid; }
    bnd[g] = lo;
}

__global__ void group_kernel(const float* __restrict__ gate, const int* __restrict__ bnd,
                             const float* __restrict__ T, float* __restrict__ ebuf,
                             float* __restrict__ gatt)
{
    __shared__ float red[256];
    __shared__ float s_mx, s_den;
    const int g = blockIdx.x;
    const int s = bnd[g], e = bnd[g + 1];
    const int t = threadIdx.x;
    float mx = -1e30f;
    for (int i = s + t; i < e; i += 256) mx = fmaxf(mx, gate[i]);
    red[t] = mx; __syncthreads();
    for (int o = 128; o; o >>= 1) { if (t < o) red[t] = fmaxf(red[t], red[t + o]); __syncthreads(); }
    if (t == 0) s_mx = red[0];
    __syncthreads();
    float den = 0.f;
    for (int i = s + t; i < e; i += 256) { float ex = __expf(gate[i] - s_mx); ebuf[i] = ex; den += ex; }
    red[t] = den; __syncthreads();
    for (int o = 128; o; o >>= 1) { if (t < o) red[t] += red[t + o]; __syncthreads(); }
    if (t == 0) s_den = red[0];
    __syncthreads();
    if (t < 128) {
        float acc = 0.f;
        for (int i = s; i < e; i++) acc += ebuf[i] * T[(size_t)i * 128 + t];
        gatt[g * 128 + t] = (e > s) ? (acc / s_den) : 0.f;
    }
}

// ---------------- launch ----------------
extern "C" void kernel_launch(void* const* d_in, const int* in_sizes, int n_in,
                              void* d_out, int out_size)
{
    const float* V_in  = (const float*)d_in[0];
    const float* F_in  = (const float*)d_in[1];
    const int*   eidx  = (const int*)d_in[2];
    const int*   batch = (const int*)d_in[4];
    const float* Wm_vf = (const float*)d_in[5];
    const float* bm_vf = (const float*)d_in[6];
    const float* Wc_vf = (const float*)d_in[7];
    const float* bc_vf = (const float*)d_in[8];
    const float* Wm_fv = (const float*)d_in[9];
    const float* bm_fv = (const float*)d_in[10];
    const float* Wc_fv = (const float*)d_in[11];
    const float* bc_fv = (const float*)d_in[12];
    const float* Wg    = (const float*)d_in[13];
    const float* bg    = (const float*)d_in[14];
    const float* Wt    = (const float*)d_in[15];
    const float* bt    = (const float*)d_in[16];
    const float* Wl    = (const float*)d_in[17];
    const float* bl    = (const float*)d_in[18];

    const int NV = in_sizes[0] / D128;
    const int NF = in_sizes[1] / D128;
    const int E  = in_sizes[2] / 2;
    const int G  = out_size / D128 - NV - NF;
    const int* src  = eidx;
    const int* dstf = eidx + E;

    float *bufA, *bufB, *bufC, *bufD, *aggrF, *aggrV, *Vc, *Fc, *WTb, *gatt, *gateArr, *ebuf;
    int *offF, *offV, *curF, *curV, *adjF, *adjV, *bnd;
    cudaGetSymbolAddress((void**)&bufA,  d_bufA);
    cudaGetSymbolAddress((void**)&bufB,  d_bufB);
    cudaGetSymbolAddress((void**)&bufC,  d_bufC);
    cudaGetSymbolAddress((void**)&bufD,  d_bufD);
    cudaGetSymbolAddress((void**)&aggrF, d_aggrF);
    cudaGetSymbolAddress((void**)&aggrV, d_aggrV);
    cudaGetSymbolAddress((void**)&Vc,    d_Vc);
    cudaGetSymbolAddress((void**)&Fc,    d_Fc);
    cudaGetSymbolAddress((void**)&WTb,   d_WT);
    cudaGetSymbolAddress((void**)&gatt,  d_gatt);
    cudaGetSymbolAddress((void**)&gateArr, d_gate);
    cudaGetSymbolAddress((void**)&ebuf,  d_ebuf);
    cudaGetSymbolAddress((void**)&offF,  d_offF);
    cudaGetSymbolAddress((void**)&offV,  d_offV);
    cudaGetSymbolAddress((void**)&curF,  d_curF);
    cudaGetSymbolAddress((void**)&curV,  d_curV);
    cudaGetSymbolAddress((void**)&adjF,  d_adjF);
    cudaGetSymbolAddress((void**)&adjV,  d_adjV);
    cudaGetSymbolAddress((void**)&bnd,   d_bnd);

    const size_t SHM = (size_t)2 * STAGE_F * sizeof(float);   // 73728
    cudaFuncSetAttribute(gemm_mma, cudaFuncAttributeMaxDynamicSharedMemorySize, (int)SHM);

    // ---- CSR build ----
    cudaMemsetAsync(curF, 0, (size_t)NF * sizeof(int));
    cudaMemsetAsync(curV, 0, (size_t)NV * sizeof(int));
    hist_kernel<<<(E + 255) / 256, 256>>>(src, dstf, E, curV, curF);
    scan2_kernel<<<2, 1024>>>(curF, offF, NF, curV, offV, NV);
    scatter_kernel<<<(E + 255) / 256, 256>>>(src, dstf, E, curV, curF, adjV, adjF);

    // ---- weight transposes into d_WT ----
    const size_t L_STRIDE = 131072;
    dim3 tb(32, 8);
    for (int l = 0; l < 2; l++) {
        const float* WmVF = Wm_vf + (size_t)l * 256 * 128;
        const float* WmFV = Wm_fv + (size_t)l * 256 * 128;
        const float* WcVF = Wc_vf + (size_t)l * 256 * 128;
        const float* WcFV = Wc_fv + (size_t)l * 256 * 128;
        float* msgF = WTb + l * L_STRIDE;
        float* msgV = msgF + 32768;
        float* updF = msgF + 65536;
        float* updV = msgF + 98304;
        transpose_kernel<<<dim3(4, 4), tb>>>(WmVF,             msgF,              128);  // Pf
        transpose_kernel<<<dim3(4, 4), tb>>>(WmFV + 128 * 128, msgF + 128 * 128,  128);  // Qf
        transpose_kernel<<<dim3(4, 4), tb>>>(WmVF + 128 * 128, msgV,              128);  // Pv
        transpose_kernel<<<dim3(4, 4), tb>>>(WmFV,             msgV + 128 * 128,  128);  // Qv
        transpose_kernel<<<dim3(8, 4), tb>>>(WcVF,             updF,              256);
        transpose_kernel<<<dim3(8, 4), tb>>>(WcFV,             updV,              256);
    }
    float* wt_t = WTb + 262144;
    float* wl_t = WTb + 278528;
    transpose_kernel<<<dim3(4, 4), tb>>>(Wt, wt_t, 128);
    transpose_kernel<<<dim3(4, 4), tb>>>(Wl, wl_t, 128);   // top half of Wl (g_prev = 0)

    const int gF = (NF + 127) / 128;
    const int gV = (NV + 127) / 128;

    float* outV_final = (float*)d_out;
    float* outF_final = (float*)d_out + (size_t)NV * D128;
    float* g_out      = (float*)d_out + (size_t)(NV + NF) * D128;

    const float* Vp = V_in;
    const float* Fp = F_in;

    for (int l = 0; l < 2; l++) {
        float* msgF = WTb + l * L_STRIDE;
        float* msgV = msgF + 32768;
        float* updF = msgF + 65536;
        float* updV = msgF + 98304;

        // fused projections: Pf,Qf from F ; Pv,Qv from V   (N=256 via gridDim.y=2)
        gemm_mma<<<dim3(gF, 2), 512, SHM>>>(Fp, nullptr, msgF, nullptr, nullptr, bufA, bufC, NF, 128, 0);
        gemm_mma<<<dim3(gV, 2), 512, SHM>>>(Vp, nullptr, msgV, nullptr, nullptr, bufB, bufD, NV, 128, 0);
        // aggregations
        csr_reduce_kernel<<<(NF + 7) / 8, 256>>>(offF, adjF, bufA, bufB, bm_vf + l * 128, aggrF, NF);
        csr_reduce_kernel<<<(NV + 7) / 8, 256>>>(offV, adjV, bufD, bufC, bm_fv + l * 128, aggrV, NV);

        float* oF = (l == 1) ? outF_final : Fc;
        float* oV = (l == 1) ? outV_final : Vc;
        // newF = relu([F, aggrF] @ Wc_vf + bc)
        gemm_mma<<<dim3(gF, 1), 512, SHM>>>(Fp, aggrF, updF, bc_vf + l * 128, nullptr, oF, nullptr, NF, 256, 1);
        // newV = V + relu([V, aggrV] @ Wc_fv + bc)
        gemm_mma<<<dim3(gV, 1), 512, SHM>>>(Vp, aggrV, updV, bc_fv + l * 128, Vp, oV, nullptr, NV, 256, 1);
        Fp = oF; Vp = oV;
    }

    // ---- global node ----
    gate_kernel<<<(NF + 7) / 8, 256>>>(Fp, Wg, bg, gateArr, NF);
    gemm_mma<<<dim3(gF, 1), 512, SHM>>>(Fp, nullptr, wt_t, bt, nullptr, bufA, nullptr, NF, 128, 0);  // T = F@Wt + bt
    bounds_kernel<<<1, 128>>>(batch, NF, G, bnd);
    group_kernel<<<G, 256>>>(gateArr, bnd, bufA, ebuf, gatt);
    gemm_mma<<<dim3(1, 1), 512, SHM>>>(gatt, nullptr, wl_t, bl, nullptr, g_out, nullptr, G, 128, 1);
}

// round 4
// speedup vs baseline: 1.9009x; 1.2414x over previous
#include <cuda_runtime.h>
#include <cstdint>
#include <cstddef>

#define MAXN 100000
#define MAXE 800000
#define D128 128

// ---------------- scratch (no allocs allowed) ----------------
__device__ float d_bufA[(size_t)MAXN * D128];   // Pf / T
__device__ float d_bufB[(size_t)MAXN * D128];   // Pv
__device__ float d_bufC[(size_t)MAXN * D128];   // Qf
__device__ float d_bufD[(size_t)MAXN * D128];   // Qv
__device__ float d_aggrF[(size_t)MAXN * D128];
__device__ float d_aggrV[(size_t)MAXN * D128];
__device__ float d_Vc[(size_t)MAXN * D128];
__device__ float d_Fc[(size_t)MAXN * D128];
__device__ float d_WT[294912];                  // pre-transposed weights (tf32 bits)
__device__ float d_gatt[64 * D128];
__device__ float d_gate[MAXN];
__device__ float d_ebuf[MAXN];
__device__ int   d_offF[MAXN + 1];
__device__ int   d_offV[MAXN + 1];
__device__ int   d_curF[MAXN];
__device__ int   d_curV[MAXN];
__device__ int   d_adjF[MAXE];
__device__ int   d_adjV[MAXE];
__device__ int   d_bnd[65 + 4];
__device__ int   d_partF[132];
__device__ int   d_partV[132];

// ---------------- PTX helpers ----------------
__device__ __forceinline__ uint32_t smem_u32(const void* p) {
    uint32_t a;
    asm("{ .reg .u64 t; cvta.to.shared.u64 t, %1; cvt.u32.u64 %0, t; }" : "=r"(a) : "l"(p));
    return a;
}
__device__ __forceinline__ uint32_t f2tf(float x) {
    uint32_t r;
    asm("cvt.rn.tf32.f32 %0, %1;" : "=r"(r) : "f"(x));
    return r;
}
__device__ __forceinline__ void ldsm_x4(uint32_t& r0, uint32_t& r1, uint32_t& r2, uint32_t& r3, uint32_t addr) {
    asm volatile("ldmatrix.sync.aligned.m8n8.x4.shared.b16 {%0,%1,%2,%3}, [%4];"
                 : "=r"(r0), "=r"(r1), "=r"(r2), "=r"(r3) : "r"(addr));
}
__device__ __forceinline__ void mma_tf32(float* c, const uint32_t* a, uint32_t b0, uint32_t b1) {
    asm volatile(
        "mma.sync.aligned.m16n8k8.row.col.f32.tf32.tf32.f32 "
        "{%0,%1,%2,%3}, {%4,%5,%6,%7}, {%8,%9}, {%0,%1,%2,%3};"
        : "+f"(c[0]), "+f"(c[1]), "+f"(c[2]), "+f"(c[3])
        : "r"(a[0]), "r"(a[1]), "r"(a[2]), "r"(a[3]), "r"(b0), "r"(b1));
}

// ---------------- tf32 mma.sync GEMM, BK=64, 1 sync / chunk ----------------
// Out[M,N] = op( A[M,K] @ WT^T + bias ); WT is [N,K] row-major, tf32 bits.
// K in {128,256}: chunks 0-1 read A0[M,128], 2-3 read A1[M,128].
// blockIdx.y: 0 -> Out0, 1 -> Out1 (each [M,128]); relu before Res; Res after relu.
#define PIT 68
#define STG (2 * 128 * PIT)   // floats per stage (A + B)
__global__ void __launch_bounds__(512, 1) gemm_mma(
    const float* __restrict__ A0, const float* __restrict__ A1,
    const float* __restrict__ WT,
    const float* __restrict__ bias, const float* __restrict__ Res,
    float* __restrict__ Out0, float* __restrict__ Out1,
    int M, int K, int relu)
{
    extern __shared__ __align__(16) float sm[];
    const int tid  = threadIdx.x;
    const int lane = tid & 31;
    const int warp = tid >> 5;
    const int wm = warp & 7;
    const int wn = warp >> 3;
    const int rowBase = blockIdx.x * 128;
    const float* WTb = WT + (size_t)blockIdx.y * 128 * K;
    float* Out = (blockIdx.y == 0) ? Out0 : Out1;

    // global load mapping: 4 x float4 per matrix per chunk
    const int lr = tid >> 4;              // 0..31
    const int lc = (tid & 15) << 2;       // 0..60

    // ldmatrix offsets (floats, within a stage)
    const int arow = wm * 16 + (lane & 15);
    const int acol = (lane >> 4) << 2;
    const int aoff = arow * PIT + acol;
    const int bq = lane >> 3;
    const int brow0 = wn * 64 + ((bq & 2) << 2) + (lane & 7);
    const int bcol = (bq & 1) << 2;
    const int boff = brow0 * PIT + bcol;

    float acc[8][4];
#pragma unroll
    for (int nt = 0; nt < 8; nt++)
#pragma unroll
        for (int j = 0; j < 4; j++) acc[nt][j] = 0.f;

    const int nch = K >> 6;   // 2 or 4
    uint4 ra[4], rb[4];

#define LDG_CHUNK(ck)                                                                  \
    {                                                                                  \
        int kg = (ck) * 64;                                                            \
        const float* Asrc = A0;                                                        \
        if (kg >= 128) { Asrc = A1; kg -= 128; }                                       \
        _Pragma("unroll")                                                              \
        for (int h = 0; h < 4; h++) {                                                  \
            int r = lr + 32 * h;                                                       \
            int grow = rowBase + r;                                                    \
            float4 v = make_float4(0.f, 0.f, 0.f, 0.f);                                \
            if (grow < M) v = *reinterpret_cast<const float4*>(Asrc + (size_t)grow * 128 + kg + lc); \
            ra[h] = make_uint4(f2tf(v.x), f2tf(v.y), f2tf(v.z), f2tf(v.w));            \
            rb[h] = *reinterpret_cast<const uint4*>(WTb + (size_t)r * K + (ck) * 64 + lc); \
        }                                                                              \
    }

#define STS_CHUNK(s)                                                                   \
    {                                                                                  \
        float* stA = sm + (s) * STG;                                                   \
        float* stB = stA + 128 * PIT;                                                  \
        _Pragma("unroll")                                                              \
        for (int h = 0; h < 4; h++) {                                                  \
            int r = lr + 32 * h;                                                       \
            *reinterpret_cast<uint4*>(stA + r * PIT + lc) = ra[h];                     \
            *reinterpret_cast<uint4*>(stB + r * PIT + lc) = rb[h];                     \
        }                                                                              \
    }

    LDG_CHUNK(0);
    STS_CHUNK(0);
    __syncthreads();

    const uint32_t smbase = smem_u32(sm);
    for (int ck = 0; ck < nch; ck++) {
        const int s = ck & 1;
        if (ck + 1 < nch) LDG_CHUNK(ck + 1);
        const uint32_t smA = smbase + (s * STG) * 4;
        const uint32_t smB = smA + 128 * PIT * 4;
#pragma unroll
        for (int kk = 0; kk < 8; kk++) {
            uint32_t a[4];
            ldsm_x4(a[0], a[1], a[2], a[3], smA + (aoff + kk * 8) * 4);
            uint32_t b0[8], b1[8];
#pragma unroll
            for (int p = 0; p < 4; p++) {
                ldsm_x4(b0[2 * p], b1[2 * p], b0[2 * p + 1], b1[2 * p + 1],
                        smB + (boff + p * 16 * PIT + kk * 8) * 4);
            }
#pragma unroll
            for (int nt = 0; nt < 8; nt++)
                mma_tf32(acc[nt], a, b0[nt], b1[nt]);
        }
        if (ck + 1 < nch) {
            STS_CHUNK(s ^ 1);
            __syncthreads();
        }
    }

    // epilogue
    const int r0 = rowBase + wm * 16 + (lane >> 2);
    const int col2 = (lane & 3) * 2;
#pragma unroll
    for (int nt = 0; nt < 8; nt++) {
        int col = wn * 64 + nt * 8 + col2;
        float v0 = acc[nt][0], v1 = acc[nt][1], v2 = acc[nt][2], v3 = acc[nt][3];
        if (bias) {
            float b0 = bias[col], b1 = bias[col + 1];
            v0 += b0; v1 += b1; v2 += b0; v3 += b1;
        }
        if (relu) {
            v0 = fmaxf(v0, 0.f); v1 = fmaxf(v1, 0.f);
            v2 = fmaxf(v2, 0.f); v3 = fmaxf(v3, 0.f);
        }
        if (r0 < M) {
            if (Res) {
                float2 rr = *reinterpret_cast<const float2*>(Res + (size_t)r0 * 128 + col);
                v0 += rr.x; v1 += rr.y;
            }
            *reinterpret_cast<float2*>(Out + (size_t)r0 * 128 + col) = make_float2(v0, v1);
        }
        if (r0 + 8 < M) {
            if (Res) {
                float2 rr = *reinterpret_cast<const float2*>(Res + (size_t)(r0 + 8) * 128 + col);
                v2 += rr.x; v3 += rr.y;
            }
            *reinterpret_cast<float2*>(Out + (size_t)(r0 + 8) * 128 + col) = make_float2(v2, v3);
        }
    }
}

// ---------------- fused weight transposes (one launch) ----------------
// job j: dst[n*K + k] = tf32(src[k*128 + n]), K in {128,256}
struct TJobs {
    const float* src[16];
    float* dst[16];
    int K[16];
};
__global__ void transpose_all(TJobs jobs)
{
    __shared__ float t[32][33];
    const int j = blockIdx.z;
    const int K = jobs.K[j];
    const int kb = blockIdx.x * 32;
    if (kb >= K) return;
    const float* src = jobs.src[j];
    float* dst = jobs.dst[j];
    const int nb = blockIdx.y * 32;
    const int x = threadIdx.x, y = threadIdx.y;
    for (int yy = y; yy < 32; yy += 8) t[yy][x] = src[(size_t)(kb + yy) * 128 + nb + x];
    __syncthreads();
    for (int yy = y; yy < 32; yy += 8)
        dst[(size_t)(nb + yy) * K + kb + x] = __uint_as_float(f2tf(t[x][yy]));
}

// ---------------- CSR build ----------------
__global__ void hist_kernel(const int* __restrict__ src, const int* __restrict__ dst, int E,
                            int* __restrict__ degV, int* __restrict__ degF)
{
    int e = blockIdx.x * blockDim.x + threadIdx.x;
    if (e < E) {
        atomicAdd(&degV[src[e]], 1);
        atomicAdd(&degF[dst[e]], 1);
    }
}

// 3-phase scan: 1024 elements per block, 256 threads (4 elems/thread)
__device__ __forceinline__ int4 load4_guard(const int* p, int base, int N)
{
    int4 v = make_int4(0, 0, 0, 0);
    if (base + 3 < N) v = *reinterpret_cast<const int4*>(p + base);
    else if (base < N) {
        v.x = p[base];
        if (base + 1 < N) v.y = p[base + 1];
        if (base + 2 < N) v.z = p[base + 2];
    }
    return v;
}

__global__ void scan_p1(const int* __restrict__ degF, int NF, int* __restrict__ pF,
                        const int* __restrict__ degV, int NV, int* __restrict__ pV)
{
    const int* deg = blockIdx.y ? degV : degF;
    int* part = blockIdx.y ? pV : pF;
    const int N = blockIdx.y ? NV : NF;
    if (blockIdx.x * 1024 >= N) return;
    int base = blockIdx.x * 1024 + threadIdx.x * 4;
    int4 v = load4_guard(deg, base, N);
    int s = v.x + v.y + v.z + v.w;
#pragma unroll
    for (int d = 16; d; d >>= 1) s += __shfl_down_sync(~0u, s, d);
    __shared__ int ws[8];
    if ((threadIdx.x & 31) == 0) ws[threadIdx.x >> 5] = s;
    __syncthreads();
    if (threadIdx.x == 0) {
        int tt = 0;
#pragma unroll
        for (int i = 0; i < 8; i++) tt += ws[i];
        part[blockIdx.x] = tt;
    }
}

__global__ void scan_p2(int* __restrict__ pF, int nbF, int* __restrict__ pV, int nbV)
{
    __shared__ int sh[128];
    const int t = threadIdx.x;
    for (int sel = 0; sel < 2; sel++) {
        int* p = sel ? pV : pF;
        const int nb = sel ? nbV : nbF;
        int v = (t < nb) ? p[t] : 0;
        sh[t] = v;
        __syncthreads();
        int x = v;
        for (int o = 1; o < 128; o <<= 1) {
            int y = (t >= o) ? sh[t - o] : 0;
            __syncthreads();
            x += y;
            sh[t] = x;
            __syncthreads();
        }
        if (t < nb) p[t] = x - v;       // exclusive
        if (t == nb - 1) p[nb] = x;     // total
        __syncthreads();
    }
}

__global__ void scan_p3(const int* __restrict__ degF, int NF, const int* __restrict__ pF,
                        int* __restrict__ offF, int* __restrict__ curF,
                        const int* __restrict__ degV, int NV, const int* __restrict__ pV,
                        int* __restrict__ offV, int* __restrict__ curV)
{
    const int* deg = blockIdx.y ? degV : degF;
    const int* part = blockIdx.y ? pV : pF;
    int* offs = blockIdx.y ? offV : offF;
    int* cur  = blockIdx.y ? curV : curF;
    const int N = blockIdx.y ? NV : NF;
    if (blockIdx.x * 1024 >= N) return;
    int base = blockIdx.x * 1024 + threadIdx.x * 4;
    int4 v = load4_guard(deg, base, N);
    int s = v.x + v.y + v.z + v.w;
    const int lane = threadIdx.x & 31, w = threadIdx.x >> 5;
    int x = s;
#pragma unroll
    for (int o = 1; o < 32; o <<= 1) {
        int y = __shfl_up_sync(~0u, x, o);
        if (lane >= o) x += y;
    }
    __shared__ int ws[8];
    if (lane == 31) ws[w] = x;
    __syncthreads();
    if (threadIdx.x == 0) {
        int run = 0;
#pragma unroll
        for (int i = 0; i < 8; i++) { int t = ws[i]; ws[i] = run; run += t; }
    }
    __syncthreads();
    int excl = (x - s) + ws[w] + part[blockIdx.x];
    int o0 = excl, o1 = o0 + v.x, o2 = o1 + v.y, o3 = o2 + v.z;
    if (base < N)     { offs[base] = o0;     cur[base] = o0; }
    if (base + 1 < N) { offs[base + 1] = o1; cur[base + 1] = o1; }
    if (base + 2 < N) { offs[base + 2] = o2; cur[base + 2] = o2; }
    if (base + 3 < N) { offs[base + 3] = o3; cur[base + 3] = o3; }
    if (blockIdx.x == 0 && threadIdx.x == 0) offs[N] = part[(N + 1023) >> 10];
}

__global__ void scatter_kernel(const int* __restrict__ src, const int* __restrict__ dst, int E,
                               int* __restrict__ curV, int* __restrict__ curF,
                               int* __restrict__ adjV, int* __restrict__ adjF)
{
    int e = blockIdx.x * blockDim.x + threadIdx.x;
    if (e < E) {
        int s = src[e], d = dst[e];
        adjF[atomicAdd(&curF[d], 1)] = s;
        adjV[atomicAdd(&curV[s], 1)] = d;
    }
}

// ---------------- CSR gather-reduce (4-edge unroll) ----------------
__global__ void csr_reduce_kernel(const int* __restrict__ offs, const int* __restrict__ adj,
                                  const float* __restrict__ Pself, const float* __restrict__ Pother,
                                  const float* __restrict__ bias, float* __restrict__ out, int N)
{
    int w = (blockIdx.x * blockDim.x + threadIdx.x) >> 5;
    int lane = threadIdx.x & 31;
    if (w >= N) return;
    const int c = lane * 4;
    float4 s = *reinterpret_cast<const float4*>(Pself + (size_t)w * 128 + c);
    float4 b = *reinterpret_cast<const float4*>(bias + c);
    s.x += b.x; s.y += b.y; s.z += b.z; s.w += b.w;
    float4 acc = make_float4(0.f, 0.f, 0.f, 0.f);
    int e = offs[w], e1 = offs[w + 1];
    for (; e + 3 < e1; e += 4) {
        int n0 = __ldg(adj + e), n1 = __ldg(adj + e + 1);
        int n2 = __ldg(adj + e + 2), n3 = __ldg(adj + e + 3);
        float4 o0 = *reinterpret_cast<const float4*>(Pother + (size_t)n0 * 128 + c);
        float4 o1 = *reinterpret_cast<const float4*>(Pother + (size_t)n1 * 128 + c);
        float4 o2 = *reinterpret_cast<const float4*>(Pother + (size_t)n2 * 128 + c);
        float4 o3 = *reinterpret_cast<const float4*>(Pother + (size_t)n3 * 128 + c);
        acc.x += fmaxf(s.x + o0.x, 0.f) + fmaxf(s.x + o1.x, 0.f) + fmaxf(s.x + o2.x, 0.f) + fmaxf(s.x + o3.x, 0.f);
        acc.y += fmaxf(s.y + o0.y, 0.f) + fmaxf(s.y + o1.y, 0.f) + fmaxf(s.y + o2.y, 0.f) + fmaxf(s.y + o3.y, 0.f);
        acc.z += fmaxf(s.z + o0.z, 0.f) + fmaxf(s.z + o1.z, 0.f) + fmaxf(s.z + o2.z, 0.f) + fmaxf(s.z + o3.z, 0.f);
        acc.w += fmaxf(s.w + o0.w, 0.f) + fmaxf(s.w + o1.w, 0.f) + fmaxf(s.w + o2.w, 0.f) + fmaxf(s.w + o3.w, 0.f);
    }
    for (; e < e1; e++) {
        int n0 = __ldg(adj + e);
        float4 o0 = *reinterpret_cast<const float4*>(Pother + (size_t)n0 * 128 + c);
        acc.x += fmaxf(s.x + o0.x, 0.f);
        acc.y += fmaxf(s.y + o0.y, 0.f);
        acc.z += fmaxf(s.z + o0.z, 0.f);
        acc.w += fmaxf(s.w + o0.w, 0.f);
    }
    *reinterpret_cast<float4*>(out + (size_t)w * 128 + c) = acc;
}

// ---------------- global node ----------------
__global__ void gate_kernel(const float* __restrict__ F, const float* __restrict__ Wg,
                            const float* __restrict__ bg, float* __restrict__ gate, int N)
{
    int w = (blockIdx.x * blockDim.x + threadIdx.x) >> 5;
    int lane = threadIdx.x & 31;
    if (w >= N) return;
    float4 f = *reinterpret_cast<const float4*>(F + (size_t)w * 128 + lane * 4);
    float4 g = *reinterpret_cast<const float4*>(Wg + lane * 4);
    float p = f.x * g.x + f.y * g.y + f.z * g.z + f.w * g.w;
#pragma unroll
    for (int d = 16; d; d >>= 1) p += __shfl_down_sync(~0u, p, d);
    if (lane == 0) gate[w] = p + bg[0];
}

__global__ void bounds_kernel(const int* __restrict__ batch, int NF, int G, int* __restrict__ bnd)
{
    int g = threadIdx.x;
    if (g > G) return;
    int lo = 0, hi = NF;
    while (lo < hi) { int mid = (lo + hi) >> 1; if (batch[mid] < g) lo = mid + 1; else hi = mid; }
    bnd[g] = lo;
}

__global__ void group_kernel(const float* __restrict__ gate, const int* __restrict__ bnd,
                             const float* __restrict__ T, float* __restrict__ ebuf,
                             float* __restrict__ gatt)
{
    __shared__ float red[256];
    __shared__ float s_mx, s_den;
    const int g = blockIdx.x;
    const int s = bnd[g], e = bnd[g + 1];
    const int t = threadIdx.x;
    float mx = -1e30f;
    for (int i = s + t; i < e; i += 256) mx = fmaxf(mx, gate[i]);
    red[t] = mx; __syncthreads();
    for (int o = 128; o; o >>= 1) { if (t < o) red[t] = fmaxf(red[t], red[t + o]); __syncthreads(); }
    if (t == 0) s_mx = red[0];
    __syncthreads();
    float den = 0.f;
    for (int i = s + t; i < e; i += 256) { float ex = __expf(gate[i] - s_mx); ebuf[i] = ex; den += ex; }
    red[t] = den; __syncthreads();
    for (int o = 128; o; o >>= 1) { if (t < o) red[t] += red[t + o]; __syncthreads(); }
    if (t == 0) s_den = red[0];
    __syncthreads();
    if (t < 128) {
        float acc = 0.f;
        for (int i = s; i < e; i++) acc += ebuf[i] * T[(size_t)i * 128 + t];
        gatt[g * 128 + t] = (e > s) ? (acc / s_den) : 0.f;
    }
}

// ---------------- launch ----------------
extern "C" void kernel_launch(void* const* d_in, const int* in_sizes, int n_in,
                              void* d_out, int out_size)
{
    const float* V_in  = (const float*)d_in[0];
    const float* F_in  = (const float*)d_in[1];
    const int*   eidx  = (const int*)d_in[2];
    const int*   batch = (const int*)d_in[4];
    const float* Wm_vf = (const float*)d_in[5];
    const float* bm_vf = (const float*)d_in[6];
    const float* Wc_vf = (const float*)d_in[7];
    const float* bc_vf = (const float*)d_in[8];
    const float* Wm_fv = (const float*)d_in[9];
    const float* bm_fv = (const float*)d_in[10];
    const float* Wc_fv = (const float*)d_in[11];
    const float* bc_fv = (const float*)d_in[12];
    const float* Wg    = (const float*)d_in[13];
    const float* bg    = (const float*)d_in[14];
    const float* Wt    = (const float*)d_in[15];
    const float* bt    = (const float*)d_in[16];
    const float* Wl    = (const float*)d_in[17];
    const float* bl    = (const float*)d_in[18];

    const int NV = in_sizes[0] / D128;
    const int NF = in_sizes[1] / D128;
    const int E  = in_sizes[2] / 2;
    const int G  = out_size / D128 - NV - NF;
    const int* src  = eidx;
    const int* dstf = eidx + E;

    float *bufA, *bufB, *bufC, *bufD, *aggrF, *aggrV, *Vc, *Fc, *WTb, *gatt, *gateArr, *ebuf;
    int *offF, *offV, *curF, *curV, *adjF, *adjV, *bnd, *pF, *pV;
    cudaGetSymbolAddress((void**)&bufA,  d_bufA);
    cudaGetSymbolAddress((void**)&bufB,  d_bufB);
    cudaGetSymbolAddress((void**)&bufC,  d_bufC);
    cudaGetSymbolAddress((void**)&bufD,  d_bufD);
    cudaGetSymbolAddress((void**)&aggrF, d_aggrF);
    cudaGetSymbolAddress((void**)&aggrV, d_aggrV);
    cudaGetSymbolAddress((void**)&Vc,    d_Vc);
    cudaGetSymbolAddress((void**)&Fc,    d_Fc);
    cudaGetSymbolAddress((void**)&WTb,   d_WT);
    cudaGetSymbolAddress((void**)&gatt,  d_gatt);
    cudaGetSymbolAddress((void**)&gateArr, d_gate);
    cudaGetSymbolAddress((void**)&ebuf,  d_ebuf);
    cudaGetSymbolAddress((void**)&offF,  d_offF);
    cudaGetSymbolAddress((void**)&offV,  d_offV);
    cudaGetSymbolAddress((void**)&curF,  d_curF);
    cudaGetSymbolAddress((void**)&curV,  d_curV);
    cudaGetSymbolAddress((void**)&adjF,  d_adjF);
    cudaGetSymbolAddress((void**)&adjV,  d_adjV);
    cudaGetSymbolAddress((void**)&bnd,   d_bnd);
    cudaGetSymbolAddress((void**)&pF,    d_partF);
    cudaGetSymbolAddress((void**)&pV,    d_partV);

    const size_t SHM = (size_t)2 * STG * sizeof(float);   // 139264
    cudaFuncSetAttribute(gemm_mma, cudaFuncAttributeMaxDynamicSharedMemorySize, (int)SHM);

    // ---- CSR build ----
    cudaMemsetAsync(curF, 0, (size_t)NF * sizeof(int));
    cudaMemsetAsync(curV, 0, (size_t)NV * sizeof(int));
    hist_kernel<<<(E + 255) / 256, 256>>>(src, dstf, E, curV, curF);
    const int nbF = (NF + 1023) >> 10, nbV = (NV + 1023) >> 10;
    const int nbMax = nbF > nbV ? nbF : nbV;
    scan_p1<<<dim3(nbMax, 2), 256>>>(curF, NF, pF, curV, NV, pV);
    scan_p2<<<1, 128>>>(pF, nbF, pV, nbV);
    scan_p3<<<dim3(nbMax, 2), 256>>>(curF, NF, pF, offF, curF, curV, NV, pV, offV, curV);
    scatter_kernel<<<(E + 255) / 256, 256>>>(src, dstf, E, curV, curF, adjV, adjF);

    // ---- fused weight transposes (tf32 bits) ----
    const size_t L_STRIDE = 131072;
    TJobs jobs{};
    int nj = 0;
    for (int l = 0; l < 2; l++) {
        const float* WmVF = Wm_vf + (size_t)l * 256 * 128;
        const float* WmFV = Wm_fv + (size_t)l * 256 * 128;
        const float* WcVF = Wc_vf + (size_t)l * 256 * 128;
        const float* WcFV = Wc_fv + (size_t)l * 256 * 128;
        float* msgF = WTb + l * L_STRIDE;
        float* msgV = msgF + 32768;
        float* updF = msgF + 65536;
        float* updV = msgF + 98304;
        jobs.src[nj] = WmVF;             jobs.dst[nj] = msgF;             jobs.K[nj++] = 128;  // Pf
        jobs.src[nj] = WmFV + 128 * 128; jobs.dst[nj] = msgF + 128 * 128; jobs.K[nj++] = 128;  // Qf
        jobs.src[nj] = WmVF + 128 * 128; jobs.dst[nj] = msgV;             jobs.K[nj++] = 128;  // Pv
        jobs.src[nj] = WmFV;             jobs.dst[nj] = msgV + 128 * 128; jobs.K[nj++] = 128;  // Qv
        jobs.src[nj] = WcVF;             jobs.dst[nj] = updF;             jobs.K[nj++] = 256;
        jobs.src[nj] = WcFV;             jobs.dst[nj] = updV;             jobs.K[nj++] = 256;
    }
    float* wt_t = WTb + 262144;
    float* wl_t = WTb + 278528;
    jobs.src[nj] = Wt; jobs.dst[nj] = wt_t; jobs.K[nj++] = 128;
    jobs.src[nj] = Wl; jobs.dst[nj] = wl_t; jobs.K[nj++] = 128;   // top half of Wl (g_prev = 0)
    transpose_all<<<dim3(8, 4, nj), dim3(32, 8)>>>(jobs);

    const int gF = (NF + 127) / 128;
    const int gV = (NV + 127) / 128;

    float* outV_final = (float*)d_out;
    float* outF_final = (float*)d_out + (size_t)NV * D128;
    float* g_out      = (float*)d_out + (size_t)(NV + NF) * D128;

    const float* Vp = V_in;
    const float* Fp = F_in;

    for (int l = 0; l < 2; l++) {
        float* msgF = WTb + l * L_STRIDE;
        float* msgV = msgF + 32768;
        float* updF = msgF + 65536;
        float* updV = msgF + 98304;

        // fused projections: Pf,Qf from F ; Pv,Qv from V   (N=256 via gridDim.y=2)
        gemm_mma<<<dim3(gF, 2), 512, SHM>>>(Fp, nullptr, msgF, nullptr, nullptr, bufA, bufC, NF, 128, 0);
        gemm_mma<<<dim3(gV, 2), 512, SHM>>>(Vp, nullptr, msgV, nullptr, nullptr, bufB, bufD, NV, 128, 0);
        // aggregations
        csr_reduce_kernel<<<(NF + 7) / 8, 256>>>(offF, adjF, bufA, bufB, bm_vf + l * 128, aggrF, NF);
        csr_reduce_kernel<<<(NV + 7) / 8, 256>>>(offV, adjV, bufD, bufC, bm_fv + l * 128, aggrV, NV);

        float* oF = (l == 1) ? outF_final : Fc;
        float* oV = (l == 1) ? outV_final : Vc;
        // newF = relu([F, aggrF] @ Wc_vf + bc)
        gemm_mma<<<dim3(gF, 1), 512, SHM>>>(Fp, aggrF, updF, bc_vf + l * 128, nullptr, oF, nullptr, NF, 256, 1);
        // newV = V + relu([V, aggrV] @ Wc_fv + bc)
        gemm_mma<<<dim3(gV, 1), 512, SHM>>>(Vp, aggrV, updV, bc_fv + l * 128, Vp, oV, nullptr, NV, 256, 1);
        Fp = oF; Vp = oV;
    }

    // ---- global node ----
    gate_kernel<<<(NF + 7) / 8, 256>>>(Fp, Wg, bg, gateArr, NF);
    gemm_mma<<<dim3(gF, 1), 512, SHM>>>(Fp, nullptr, wt_t, bt, nullptr, bufA, nullptr, NF, 128, 0);  // T = F@Wt + bt
    bounds_kernel<<<1, 128>>>(batch, NF, G, bnd);
    group_kernel<<<G, 256>>>(gateArr, bnd, bufA, ebuf, gatt);
    gemm_mma<<<dim3(1, 1), 512, SHM>>>(gatt, nullptr, wl_t, bl, nullptr, g_out, nullptr, G, 128, 1);
}